// round 5
// baseline (speedup 1.0000x reference)
#include <cuda_runtime.h>
#include <math.h>

#define B_ 8
#define C_ 64
#define H_ 256
#define W_ 512
#define KF 64            // modified W-frequency bins
#define NROW (B_*C_*H_)  // 131072 GEMM rows

// ---------------- static device scratch (allocation-free rule) ----------------
__device__ __align__(16) float  d_TF[W_ * 2 * KF];              // fwd twiddles [w][2k]
__device__ __align__(16) float  d_TI[2 * KF * W_];              // inv twiddles [2k][w]
__device__ __align__(16) float2 d_E[W_];                        // e^{2*pi*i*t/512}
__device__ __align__(16) float  d_xp[(size_t)NROW * KF];        // pooled x (b,c,h,j)
__device__ __align__(16) float2 d_G[B_ * H_ * KF];              // filt-1 (b,m,k)
__device__ __align__(16) float2 d_ker[B_ * KF * H_];            // circulant kernel (b,k,d)
__device__ __align__(16) float  d_U[(size_t)NROW * 2 * KF];     // fwd spectrum (b,c,h,k{r,i})
__device__ __align__(16) float2 d_U2[(size_t)B_ * KF * C_ * H_];// (b,k,c,h)
__device__ __align__(16) float2 d_V2[(size_t)B_ * KF * C_ * H_];// (b,k,c,n)
__device__ __align__(16) float  d_V[(size_t)NROW * 2 * KF];     // (b,c,n,k{r,i})

// ---------------- twiddle tables (double-precision generation) ----------------
__global__ void k_tables() {
    int t = blockIdx.x * 256 + threadIdx.x;     // 65536 threads
    if (t < 512) {
        double s, c; sincospi((double)t / 256.0, &s, &c);
        d_E[t] = make_float2((float)c, (float)s);
    }
    {   // TF[w][kk]: kk=2k -> cos(2pi wk/512), kk=2k+1 -> -sin
        int w = t >> 7, kk = t & 127, k = kk >> 1;
        int m = (w * k) & 511;
        double s, c; sincospi((double)m / 256.0, &s, &c);
        d_TF[t] = (kk & 1) ? (float)(-s) : (float)c;
    }
    {   // TI[kk][w]: kk=2k -> ck*cos, kk=2k+1 -> -ck*sin  (c0=1, ck=2)
        int kk = t >> 9, w = t & 511, k = kk >> 1;
        int m = (w * k) & 511;
        double s, c; sincospi((double)m / 256.0, &s, &c);
        float ck = (k == 0) ? 1.f : 2.f;
        d_TI[t] = (kk & 1) ? (float)(-ck * s) : (float)(ck * c);
    }
}

// ---------------- pooling: xp[b,c,h,j] = mean_{u<8} x[..., 8j+u] ----------------
__global__ void k_pool(const float* __restrict__ x) {
    int id = blockIdx.x * 256 + threadIdx.x;    // NROW*64 exactly
    int j = id & 63;
    size_t row = (size_t)(id >> 6);
    const float* p = x + row * W_ + j * 8;
    float4 a = *(const float4*)p, b = *(const float4*)(p + 4);
    d_xp[id] = (a.x + a.y + a.z + a.w + b.x + b.y + b.z + b.w) * 0.125f;
}

// ---------------- generic tiled GEMM: C[64xN128] = scale*A*B (+X) ----------------
template<bool ADDX>
__global__ void __launch_bounds__(256) k_gemm(
    const float* __restrict__ A, int lda,
    const float* __restrict__ Bm, int ldb,
    float* __restrict__ C, int ldc,
    const float* __restrict__ X, int K, float scale)
{
    __shared__ float As[32][65];
    __shared__ float Bs[32][128];
    const int tid = threadIdx.x;
    const int tx = tid & 15;        // cols tx + 16*v
    const int ty = tid >> 4;        // rows ty*4 + u
    const long row0 = (long)blockIdx.x * 64;
    const int col0 = blockIdx.y * 128;

    float acc[4][8];
#pragma unroll
    for (int u = 0; u < 4; u++)
#pragma unroll
        for (int v = 0; v < 8; v++) acc[u][v] = 0.f;

    for (int kc = 0; kc < K; kc += 32) {
        __syncthreads();
#pragma unroll
        for (int i = 0; i < 2; i++) {           // A tile 64x32 (transposed)
            int f = tid + i * 256;
            int r = f >> 3, q = f & 7;
            float4 v = *(const float4*)(A + (row0 + r) * lda + kc + q * 4);
            As[q * 4 + 0][r] = v.x; As[q * 4 + 1][r] = v.y;
            As[q * 4 + 2][r] = v.z; As[q * 4 + 3][r] = v.w;
        }
#pragma unroll
        for (int i = 0; i < 4; i++) {           // B tile 32x128
            int f = tid + i * 256;
            int kk = f >> 5, q = f & 31;
            *(float4*)&Bs[kk][q * 4] =
                *(const float4*)(Bm + (long)(kc + kk) * ldb + col0 + q * 4);
        }
        __syncthreads();
#pragma unroll
        for (int kk = 0; kk < 32; kk++) {
            float a[4], b[8];
#pragma unroll
            for (int u = 0; u < 4; u++) a[u] = As[kk][ty * 4 + u];
#pragma unroll
            for (int v = 0; v < 8; v++) b[v] = Bs[kk][tx + 16 * v];
#pragma unroll
            for (int u = 0; u < 4; u++)
#pragma unroll
                for (int v = 0; v < 8; v++) acc[u][v] = fmaf(a[u], b[v], acc[u][v]);
        }
    }
#pragma unroll
    for (int u = 0; u < 4; u++)
#pragma unroll
        for (int v = 0; v < 8; v++) {
            long idx = (row0 + ty * 4 + u) * ldc + col0 + tx + 16 * v;
            float val = acc[u][v] * scale;
            if (ADDX) val += X[idx];
            C[idx] = val;
        }
}

// ---------------- filter: params GEMV + nonlinearities -> G = filt-1 ----------------
__global__ void __launch_bounds__(256) k_filter(
    const float* __restrict__ w, const float* __restrict__ bias,
    const float* __restrict__ dt)
{
    __shared__ float ws[4096];
    __shared__ float bs[64];
    int tid = threadIdx.x;
#pragma unroll
    for (int i = tid; i < 4096; i += 256) ws[i] = w[i];
    if (tid < 64) bs[tid] = bias[tid];
    __syncthreads();

    int id = blockIdx.x * 256 + tid;            // B*H*64 = 131072
    int j = id & 63, h = (id >> 6) & 255, bb = id >> 14;
    float xv[64];
#pragma unroll
    for (int c = 0; c < 64; c++)
        xv[c] = d_xp[(((size_t)(bb * 64 + c)) * 256 + h) * 64 + j];
    float dtb = dt[bb];
    float fr = 0.f, fi = 0.f;
    for (int r = 0; r < 32; r++) {
        float p1 = bs[r], p2 = bs[32 + r];
#pragma unroll
        for (int c = 0; c < 64; c++) {
            p1 = fmaf(ws[r * 64 + c], xv[c], p1);
            p2 = fmaf(ws[(32 + r) * 64 + c], xv[c], p2);
        }
        float nu  = log1pf(expf(p1));
        float th  = tanhf(p2) * 3.14159265358979323846f;
        float dec = expf(-nu * dtb);
        float s, co; sincosf(th * dtb, &s, &co);
        fr = fmaf(dec, co, fr);
        fi = fmaf(dec, s, fi);
    }
    d_G[id] = make_float2(fr - 1.f, fi);
}

// ---------------- circulant kernel: ker[b,k,d] = (1/256) sum_m G[b,m,k] e^{+2pi i dm/256} ----
__global__ void k_kern() {
    __shared__ float2 Gs[256];
    __shared__ float2 Es[256];
    int bk = blockIdx.x;                        // b*64+k
    int b = bk >> 6, k = bk & 63;
    int d = threadIdx.x;
    Gs[d] = d_G[((size_t)b * 256 + d) * 64 + k];
    Es[d] = d_E[2 * d];                         // e^{2pi i d/256}
    __syncthreads();
    float ar = 0.f, ai = 0.f;
    for (int m = 0; m < 256; m++) {
        int t = (d * m) & 255;
        float2 e = Es[t]; float2 g = Gs[m];
        ar += g.x * e.x - g.y * e.y;
        ai += g.x * e.y + g.y * e.x;
    }
    d_ker[(size_t)bk * 256 + d] = make_float2(ar * (1.f / 256.f), ai * (1.f / 256.f));
}

// ---------------- batched complex transpose: in (b,R,C) -> out (b,C,R) ----------------
__global__ void k_transpose(const float2* __restrict__ in, float2* __restrict__ out,
                            int R, int C)
{
    __shared__ float2 t[32][33];
    int c0 = blockIdx.x * 32, r0 = blockIdx.y * 32;
    int x = threadIdx.x, y = threadIdx.y;       // (32,8)
    size_t base = (size_t)blockIdx.z * R * C;
#pragma unroll
    for (int i = 0; i < 32; i += 8)
        t[y + i][x] = in[base + (size_t)(r0 + y + i) * C + c0 + x];
    __syncthreads();
#pragma unroll
    for (int i = 0; i < 32; i += 8)
        out[base + (size_t)(c0 + y + i) * R + r0 + x] = t[x][y + i];
}

// ---------------- H circulant conv: V2[b,k,c,n] = sum_h ker[b,k,(n-h)&255] * U2[b,k,c,h] ----
__global__ void __launch_bounds__(256) k_circ() {
    __shared__ float2 k2[512];
    __shared__ float2 Us[16][256];
    int bk = blockIdx.x;                        // 512 blocks
    int tid = threadIdx.x;
    const float2* kb = d_ker + (size_t)bk * 256;
    k2[tid] = kb[tid & 255];
    k2[tid + 256] = kb[tid];
    const float2* Ub = d_U2 + (size_t)bk * (C_ * H_);
    float2*       Vb = d_V2 + (size_t)bk * (C_ * H_);
    int n = tid;
    for (int cc = 0; cc < 64; cc += 16) {
        __syncthreads();
#pragma unroll
        for (int i = 0; i < 16; i++) {
            int f = tid + i * 256;
            Us[f >> 8][f & 255] = Ub[(cc + (f >> 8)) * 256 + (f & 255)];
        }
        __syncthreads();
        float ar[16], ai[16];
#pragma unroll
        for (int c = 0; c < 16; c++) { ar[c] = 0.f; ai[c] = 0.f; }
#pragma unroll 4
        for (int h = 0; h < 256; h++) {
            float2 kv = k2[n - h + 256];
#pragma unroll
            for (int c = 0; c < 16; c++) {
                float2 u = Us[c][h];
                ar[c] = fmaf(kv.x, u.x, fmaf(-kv.y, u.y, ar[c]));
                ai[c] = fmaf(kv.x, u.y, fmaf( kv.y, u.x, ai[c]));
            }
        }
#pragma unroll
        for (int c = 0; c < 16; c++)
            Vb[(cc + c) * 256 + n] = make_float2(ar[c], ai[c]);
    }
}

// ---------------- launch ----------------
extern "C" void kernel_launch(void* const* d_in, const int* in_sizes, int n_in,
                              void* d_out, int out_size) {
    const float* x    = (const float*)d_in[0];
    const float* dt   = (const float*)d_in[1];
    const float* w    = (const float*)d_in[2];
    const float* bias = (const float*)d_in[3];
    float* out = (float*)d_out;

    void *pTF, *pTI, *pU, *pU2, *pV2, *pV;
    cudaGetSymbolAddress(&pTF, d_TF);
    cudaGetSymbolAddress(&pTI, d_TI);
    cudaGetSymbolAddress(&pU,  d_U);
    cudaGetSymbolAddress(&pU2, d_U2);
    cudaGetSymbolAddress(&pV2, d_V2);
    cudaGetSymbolAddress(&pV,  d_V);

    k_tables<<<256, 256>>>();
    k_pool<<<NROW * 64 / 256, 256>>>(x);
    // K1: U = x * TF   (131072 x 512) * (512 x 128)
    k_gemm<false><<<dim3(NROW / 64, 1), 256>>>(
        x, W_, (const float*)pTF, 128, (float*)pU, 128, nullptr, W_, 1.f);
    k_filter<<<B_ * H_ * KF / 256, 256>>>(w, bias, dt);
    k_kern<<<B_ * KF, 256>>>();
    // T1: (b, c*h=16384, k=64) -> (b, k, c*h)
    k_transpose<<<dim3(2, 512, B_), dim3(32, 8)>>>(
        (const float2*)pU, (float2*)pU2, 16384, 64);
    k_circ<<<B_ * KF, 256>>>();
    // T2: (b, k=64, c*n=16384) -> (b, c*n, k)
    k_transpose<<<dim3(512, 2, B_), dim3(32, 8)>>>(
        (const float2*)pV2, (float2*)pV, 64, 16384);
    // K5: out = x + (1/512) * V * TI   (131072 x 128) * (128 x 512)
    k_gemm<true><<<dim3(NROW / 64, 4), 256>>>(
        (const float*)pV, 128, (const float*)pTI, W_, out, W_, x, 128, 1.f / 512.f);
}